// round 3
// baseline (speedup 1.0000x reference)
#include <cuda_runtime.h>
#include <cuda_bf16.h>

#define BATCH 256
#define NV 10475
#define NJ 55
#define PB 486            // pose basis = 54*9
#define NC3 (NV*3)        // 31425
#define JOFF (BATCH*NC3)  // offset of joints in d_out

// ---- scratch (device globals; no allocation allowed) ----
__device__ float g_jreg[3465];            // (55, 63): [vt(3) | sh(30) | ex(30)]
__device__ float g_pf[PB * BATCH];        // pose feature, TRANSPOSED [k][b]
__device__ float g_Arel[BATCH * NJ * 12];

__constant__ int c_parents[NJ] = {
    -1, 0, 0, 0, 1, 2, 3, 4, 5, 6, 7, 8, 9, 9, 9, 12, 13, 14, 16, 17, 18, 19,
    15, 15, 15, 20, 25, 26, 20, 28, 29, 20, 31, 32, 20, 34, 35, 20, 37, 38,
    21, 40, 41, 21, 43, 44, 21, 46, 47, 21, 49, 50, 21, 52, 53};

typedef unsigned long long ull;

// ---- f32x2 helpers (FFMA2 is only reachable via PTX; exact fp32 lanewise) ----
__device__ __forceinline__ ull d_pack(float lo, float hi) {
    ull r;
    asm("mov.b64 %0, {%1, %2};" : "=l"(r)
        : "r"(__float_as_uint(lo)), "r"(__float_as_uint(hi)));
    return r;
}
__device__ __forceinline__ ull d_dup(float x) { return d_pack(x, x); }
__device__ __forceinline__ void d_unpack(ull v, float& lo, float& hi) {
    unsigned ulo, uhi;
    asm("mov.b64 {%0, %1}, %2;" : "=r"(ulo), "=r"(uhi) : "l"(v));
    lo = __uint_as_float(ulo); hi = __uint_as_float(uhi);
}
__device__ __forceinline__ ull d_fma2(ull a, ull b, ull c) {
    ull d;
    asm("fma.rn.f32x2 %0, %1, %2, %3;" : "=l"(d) : "l"(a), "l"(b), "l"(c));
    return d;
}
__device__ __forceinline__ ull d_add2(ull a, ull b) {
    ull d;
    asm("add.rn.f32x2 %0, %1, %2;" : "=l"(d) : "l"(a), "l"(b));
    return d;
}

// full_pose joint j -> source rotation matrix pointer for batch b
__device__ __forceinline__ const float* joint_R(
    int j, int b, const float* wr, const float* bp, const float* jaw,
    const float* le, const float* re, const float* lh, const float* rh)
{
    if (j == 0)  return wr + b * 9;
    if (j <= 21) return bp + (b * 21 + (j - 1)) * 9;
    if (j == 22) return jaw + b * 9;
    if (j == 23) return le + b * 9;
    if (j == 24) return re + b * 9;
    if (j <= 39) return lh + (b * 15 + (j - 25)) * 9;
    return rh + (b * 15 + (j - 40)) * 9;
}

// ---- K1: fused JR @ [vt | shapedirs | expr_dirs] -> g_jreg (55,63) ----
__global__ __launch_bounds__(256) void jr_kernel(
    const float* __restrict__ JR, const float* __restrict__ vt,
    const float* __restrict__ sh, const float* __restrict__ ex)
{
    int j = blockIdx.x;
    int tid = threadIdx.x;
    __shared__ float jr_s[256];
    __shared__ float part[256];
    int c = tid % 63;
    int g = tid / 63;
    bool active = tid < 252;
    float acc = 0.f;

    for (int v0 = 0; v0 < NV; v0 += 256) {
        int vload = v0 + tid;
        jr_s[tid] = (vload < NV) ? JR[j * NV + vload] : 0.f;
        __syncthreads();
        if (active) {
            #pragma unroll 4
            for (int vv = g; vv < 256; vv += 4) {
                int gv = v0 + vv;
                if (gv < NV) {
                    float d;
                    if (c < 3)       d = vt[gv * 3 + c];
                    else if (c < 33) d = sh[gv * 30 + (c - 3)];
                    else             d = ex[gv * 30 + (c - 33)];
                    acc += jr_s[vv] * d;
                }
            }
        }
        __syncthreads();
    }
    part[tid] = active ? acc : 0.f;
    __syncthreads();
    if (tid < 63)
        g_jreg[j * 63 + tid] =
            part[tid] + part[63 + tid] + part[126 + tid] + part[189 + tid];
}

// ---- K2: per-batch joints + kinematic chain + A_rel + joints out + pf ----
__global__ __launch_bounds__(64) void chain_kernel(
    const float* __restrict__ wr, const float* __restrict__ bp,
    const float* __restrict__ jaw, const float* __restrict__ le,
    const float* __restrict__ re, const float* __restrict__ lh,
    const float* __restrict__ rh, const float* __restrict__ shape,
    const float* __restrict__ expr, const float* __restrict__ tsl,
    float* __restrict__ out)
{
    int b = blockIdx.x;
    int tid = threadIdx.x;
    __shared__ float R_s[NJ * 9];
    __shared__ float J_s[NJ * 3];
    __shared__ float rel_s[NJ * 3];
    __shared__ float A_s[NJ * 12];

    for (int idx = tid; idx < NJ * 9; idx += 64) {
        int j = idx / 9, e = idx % 9;
        R_s[idx] = joint_R(j, b, wr, bp, jaw, le, re, lh, rh)[e];
    }
    for (int idx = tid; idx < NJ * 3; idx += 64) {
        int j = idx / 3, c = idx % 3;
        const float* base = g_jreg + j * 63;
        float v = base[c];
        #pragma unroll
        for (int k = 0; k < 10; k++) v += base[3 + c * 10 + k] * shape[b * 10 + k];
        #pragma unroll
        for (int k = 0; k < 10; k++) v += base[33 + c * 10 + k] * expr[b * 10 + k];
        J_s[idx] = v;
    }
    __syncthreads();
    for (int idx = tid; idx < NJ * 3; idx += 64) {
        int j = idx / 3, c = idx % 3;
        rel_s[idx] = J_s[idx] - ((j > 0) ? J_s[c_parents[j] * 3 + c] : 0.f);
    }
    __syncthreads();

    if (tid < 12) {
        int r = tid / 4, c = tid % 4;
        A_s[r * 4 + c] = (c < 3) ? R_s[r * 3 + c] : rel_s[r];
        __syncwarp(0x0FFF);
        for (int i = 1; i < NJ; i++) {
            int p = c_parents[i];
            const float* Ap = A_s + p * 12;
            float v;
            if (c < 3)
                v = Ap[r * 4 + 0] * R_s[i * 9 + 0 + c] +
                    Ap[r * 4 + 1] * R_s[i * 9 + 3 + c] +
                    Ap[r * 4 + 2] * R_s[i * 9 + 6 + c];
            else
                v = Ap[r * 4 + 0] * rel_s[i * 3 + 0] +
                    Ap[r * 4 + 1] * rel_s[i * 3 + 1] +
                    Ap[r * 4 + 2] * rel_s[i * 3 + 2] + Ap[r * 4 + 3];
            A_s[i * 12 + r * 4 + c] = v;
            __syncwarp(0x0FFF);
        }
    }
    __syncthreads();

    // joints output: posed + tsl
    for (int idx = tid; idx < NJ * 3; idx += 64) {
        int j = idx / 3, c = idx % 3;
        out[JOFF + b * (NJ * 3) + idx] = A_s[j * 12 + c * 4 + 3] + tsl[b * 3 + c];
    }
    // A_rel with corrected translation
    for (int idx = tid; idx < NJ * 12; idx += 64) {
        int j = idx / 12, e = idx % 12, r = e / 4, c = e % 4;
        float v;
        if (c < 3)
            v = A_s[j * 12 + r * 4 + c];
        else
            v = A_s[j * 12 + r * 4 + 3] -
                (A_s[j * 12 + r * 4 + 0] * J_s[j * 3 + 0] +
                 A_s[j * 12 + r * 4 + 1] * J_s[j * 3 + 1] +
                 A_s[j * 12 + r * 4 + 2] * J_s[j * 3 + 2]);
        g_Arel[b * (NJ * 12) + idx] = v;
    }
    // pose feature, transposed layout [r][b]
    for (int idx = tid; idx < PB; idx += 64) {
        int e = idx % 9;
        float v = R_s[9 + idx] - ((e == 0 || e == 4 || e == 8) ? 1.f : 0.f);
        g_pf[idx * BATCH + b] = v;
    }
}

// ---- K3: fused pose-blend GEMM + shape blend + LBS skinning (f32x2) ----
#define BB 32   // batches per block
#define BV 64   // vertices per block
#define KC 32   // k chunk
#define JG 10   // joints per A_rel staging group

// smem word map:
//  GEMM phase: pf_s [32][32] @0 (1024), pd_s [32][3][64] @1024 (6144) -> 7168
//  EPI  phase: sh_s [30][64] @0, ex_s @1920, vt_s [3][64] @3840,
//              be_s @4032 (320), exb_s @4352 (320)  (all dead after vp)
//              ar2  @0 (32*10*12*2 = 7680, overlaps dead region)
//              w_s  [55][64] @7680 (3520), ts_s @11200 (96) -> 11296
#define SMEM_WORDS 11296

__global__ __launch_bounds__(256, 2) void lbs_kernel(
    const float* __restrict__ posedirs, const float* __restrict__ v_template,
    const float* __restrict__ shapedirs, const float* __restrict__ expr_dirs,
    const float* __restrict__ lbsw, const float* __restrict__ body_shape,
    const float* __restrict__ expr_shape, const float* __restrict__ tsl,
    float* __restrict__ out_verts)
{
    int vt0 = blockIdx.x * BV;
    int b0 = blockIdx.y * BB;
    int tid = threadIdx.x;
    int vloc = tid & 31;
    int v2 = 2 * vloc;        // local vert pair base
    int bg = tid >> 5;        // warp id: batches bg*4..bg*4+3

    __shared__ __align__(16) float smem[SMEM_WORDS];
    float* pf_s = smem;            // [KC][BB]
    float* pd_s = smem + 1024;     // [KC][3][BV]

    ull acc2[4][3];
    #pragma unroll
    for (int i = 0; i < 4; i++)
        #pragma unroll
        for (int c = 0; c < 3; c++) acc2[i][c] = 0ull;

    int col0 = vt0 * 3;
    for (int k0 = 0; k0 < PB; k0 += KC) {
        #pragma unroll
        for (int it = 0; it < 4; it++) {
            int idx = it * 256 + tid;            // idx = k*32 + bb
            int k = idx >> 5, bb = idx & 31;
            pf_s[idx] = (k0 + k < PB) ? g_pf[(k0 + k) * BATCH + b0 + bb] : 0.f;
        }
        #pragma unroll
        for (int it = 0; it < 24; it++) {
            int idx = it * 256 + tid;
            int k = idx / 192, col = idx - k * 192;
            int v = col / 3, c = col - v * 3;
            int gc = col0 + col;
            float val = 0.f;
            if (k0 + k < PB && gc < NC3) val = posedirs[(k0 + k) * NC3 + gc];
            pd_s[k * 192 + c * 64 + v] = val;
        }
        __syncthreads();
        #pragma unroll
        for (int k = 0; k < KC; k++) {
            const float4 av = *(const float4*)(pf_s + k * 32 + bg * 4); // broadcast
            ull A0 = d_dup(av.x), A1 = d_dup(av.y), A2 = d_dup(av.z), A3 = d_dup(av.w);
            const float* row = pd_s + k * 192 + v2;
            ull p0 = *(const ull*)(row);
            ull p1 = *(const ull*)(row + 64);
            ull p2 = *(const ull*)(row + 128);
            acc2[0][0] = d_fma2(A0, p0, acc2[0][0]);
            acc2[0][1] = d_fma2(A0, p1, acc2[0][1]);
            acc2[0][2] = d_fma2(A0, p2, acc2[0][2]);
            acc2[1][0] = d_fma2(A1, p0, acc2[1][0]);
            acc2[1][1] = d_fma2(A1, p1, acc2[1][1]);
            acc2[1][2] = d_fma2(A1, p2, acc2[1][2]);
            acc2[2][0] = d_fma2(A2, p0, acc2[2][0]);
            acc2[2][1] = d_fma2(A2, p1, acc2[2][1]);
            acc2[2][2] = d_fma2(A2, p2, acc2[2][2]);
            acc2[3][0] = d_fma2(A3, p0, acc2[3][0]);
            acc2[3][1] = d_fma2(A3, p1, acc2[3][1]);
            acc2[3][2] = d_fma2(A3, p2, acc2[3][2]);
        }
        __syncthreads();
    }

    // ---- epilogue staging ----
    float* sh_s  = smem;            // [30][64]
    float* ex_s  = smem + 1920;     // [30][64]
    float* vt_s  = smem + 3840;     // [3][64]
    float* be_s  = smem + 4032;     // [32][10]
    float* exb_s = smem + 4352;     // [32][10]
    float* w_s   = smem + 7680;     // [55][64]
    float* ts_s  = smem + 11200;    // [32][3]

    for (int idx = tid; idx < 1920; idx += 256) {
        int e = idx / 64, v = idx & 63;
        int gv = vt0 + v;
        sh_s[idx] = (gv < NV) ? shapedirs[gv * 30 + e] : 0.f;
        ex_s[idx] = (gv < NV) ? expr_dirs[gv * 30 + e] : 0.f;
    }
    for (int idx = tid; idx < 192; idx += 256) {
        int c = idx / 64, v = idx & 63;
        int gv = vt0 + v;
        vt_s[idx] = (gv < NV) ? v_template[gv * 3 + c] : 0.f;
    }
    for (int idx = tid; idx < 3520; idx += 256) {
        int j = idx / 64, v = idx & 63;
        int gv = vt0 + v;
        w_s[idx] = (gv < NV) ? lbsw[gv * 55 + j] : 0.f;
    }
    for (int idx = tid; idx < 320; idx += 256) {
        int bb = idx / 10, k = idx % 10;
        be_s[idx]  = body_shape[(b0 + bb) * 10 + k];
        exb_s[idx] = expr_shape[(b0 + bb) * 10 + k];
    }
    for (int idx = tid; idx < 96; idx += 256)
        ts_s[idx] = tsl[b0 * 3 + idx];
    __syncthreads();

    // v_posed (packed over the vert pair)
    ull vp2[4][3];
    {
        ull vt2[3];
        #pragma unroll
        for (int c = 0; c < 3; c++) vt2[c] = *(const ull*)(vt_s + c * 64 + v2);
        #pragma unroll
        for (int i = 0; i < 4; i++)
            #pragma unroll
            for (int c = 0; c < 3; c++) vp2[i][c] = d_add2(acc2[i][c], vt2[c]);
        #pragma unroll
        for (int k = 0; k < 10; k++) {
            ull bed[4], exd[4];
            #pragma unroll
            for (int i = 0; i < 4; i++) {
                bed[i] = d_dup(be_s[(bg * 4 + i) * 10 + k]);
                exd[i] = d_dup(exb_s[(bg * 4 + i) * 10 + k]);
            }
            #pragma unroll
            for (int c = 0; c < 3; c++) {
                ull s2v = *(const ull*)(sh_s + (c * 10 + k) * 64 + v2);
                ull e2v = *(const ull*)(ex_s + (c * 10 + k) * 64 + v2);
                #pragma unroll
                for (int i = 0; i < 4; i++) {
                    vp2[i][c] = d_fma2(bed[i], s2v, vp2[i][c]);
                    vp2[i][c] = d_fma2(exd[i], e2v, vp2[i][c]);
                }
            }
        }
    }

    ull o2[4][3];
    #pragma unroll
    for (int i = 0; i < 4; i++)
        #pragma unroll
        for (int c = 0; c < 3; c++) o2[i][c] = 0ull;

    // skinning: A_rel staged DUPLICATED so LDS.64 yields packed scalars
    float* ar2 = smem;  // [32][JG*12*2] = 7680 words (overlaps dead sh/ex/vt/be)
    for (int j0 = 0; j0 < NJ; j0 += JG) {
        int njg = (NJ - j0 < JG) ? (NJ - j0) : JG;
        __syncthreads();
        int total = BB * njg * 12;
        for (int idx = tid; idx < total; idx += 256) {
            int bb = idx / (njg * 12);
            int rem = idx % (njg * 12);
            float val = g_Arel[(b0 + bb) * (NJ * 12) + j0 * 12 + rem];
            ar2[bb * 240 + rem * 2]     = val;
            ar2[bb * 240 + rem * 2 + 1] = val;
        }
        __syncthreads();
        for (int jj = 0; jj < njg; jj++) {
            int j = j0 + jj;
            ull w2 = *(const ull*)(w_s + j * 64 + v2);
            #pragma unroll
            for (int i = 0; i < 4; i++) {
                const float* mb = ar2 + (bg * 4 + i) * 240 + jj * 24;
                ull x2 = vp2[i][0], y2 = vp2[i][1], z2 = vp2[i][2];
                ull M0  = *(const ull*)(mb + 0),  M1  = *(const ull*)(mb + 2);
                ull M2  = *(const ull*)(mb + 4),  M3  = *(const ull*)(mb + 6);
                ull s0 = d_fma2(M0, x2, M3);
                s0 = d_fma2(M1, y2, s0);
                s0 = d_fma2(M2, z2, s0);
                o2[i][0] = d_fma2(w2, s0, o2[i][0]);
                ull M4  = *(const ull*)(mb + 8),  M5  = *(const ull*)(mb + 10);
                ull M6  = *(const ull*)(mb + 12), M7  = *(const ull*)(mb + 14);
                ull s1 = d_fma2(M4, x2, M7);
                s1 = d_fma2(M5, y2, s1);
                s1 = d_fma2(M6, z2, s1);
                o2[i][1] = d_fma2(w2, s1, o2[i][1]);
                ull M8  = *(const ull*)(mb + 16), M9  = *(const ull*)(mb + 18);
                ull M10 = *(const ull*)(mb + 20), M11 = *(const ull*)(mb + 22);
                ull s2 = d_fma2(M8, x2, M11);
                s2 = d_fma2(M9, y2, s2);
                s2 = d_fma2(M10, z2, s2);
                o2[i][2] = d_fma2(w2, s2, o2[i][2]);
            }
        }
    }

    // store
    #pragma unroll
    for (int i = 0; i < 4; i++) {
        int bl = bg * 4 + i;
        int b = b0 + bl;
        float t0 = ts_s[bl * 3], t1 = ts_s[bl * 3 + 1], t2 = ts_s[bl * 3 + 2];
        float x0, x1, y0, y1, z0, z1;
        d_unpack(o2[i][0], x0, x1);
        d_unpack(o2[i][1], y0, y1);
        d_unpack(o2[i][2], z0, z1);
        int va = vt0 + v2;
        if (va < NV) {
            float* p = out_verts + b * NC3 + va * 3;
            p[0] = x0 + t0; p[1] = y0 + t1; p[2] = z0 + t2;
        }
        if (va + 1 < NV) {
            float* p = out_verts + b * NC3 + (va + 1) * 3;
            p[0] = x1 + t0; p[1] = y1 + t1; p[2] = z1 + t2;
        }
    }
}

extern "C" void kernel_launch(void* const* d_in, const int* in_sizes, int n_in,
                              void* d_out, int out_size)
{
    const float* world_rot  = (const float*)d_in[0];
    const float* world_tsl  = (const float*)d_in[1];
    const float* body_shape = (const float*)d_in[2];
    const float* body_pose  = (const float*)d_in[3];
    const float* lhand      = (const float*)d_in[4];
    const float* rhand      = (const float*)d_in[5];
    const float* expr_shape = (const float*)d_in[6];
    const float* jaw        = (const float*)d_in[7];
    const float* leye       = (const float*)d_in[8];
    const float* reye       = (const float*)d_in[9];
    const float* v_template = (const float*)d_in[10];
    const float* shapedirs  = (const float*)d_in[11];
    const float* expr_dirs  = (const float*)d_in[12];
    const float* posedirs   = (const float*)d_in[13];
    const float* J_reg      = (const float*)d_in[14];
    const float* lbsw       = (const float*)d_in[15];
    float* out = (float*)d_out;

    jr_kernel<<<NJ, 256>>>(J_reg, v_template, shapedirs, expr_dirs);
    chain_kernel<<<BATCH, 64>>>(world_rot, body_pose, jaw, leye, reye, lhand,
                                rhand, body_shape, expr_shape, world_tsl, out);
    dim3 grid((NV + BV - 1) / BV, BATCH / BB);
    lbs_kernel<<<grid, 256>>>(posedirs, v_template, shapedirs, expr_dirs,
                              lbsw, body_shape, expr_shape, world_tsl, out);
}